// round 2
// baseline (speedup 1.0000x reference)
#include <cuda_runtime.h>
#include <math_constants.h>

#define NB 8
#define NP 4096
#define THREADS 256
#define ILX 4
#define XCHUNK (THREADS * ILX)   // 1024
#define XC (NP / XCHUNK)         // 4
#define YT 2048
#define YC (NP / YT)             // 2

// Scratch: per-point running mins for both directions, stored as float bits.
// Positive floats compare identically as signed ints -> atomicMin works.
__device__ int g_min[2 * NB * NP];

__global__ void init_min_kernel() {
    int i = blockIdx.x * blockDim.x + threadIdx.x;
    if (i < 2 * NB * NP) g_min[i] = 0x7F7FFFFF;  // FLT_MAX bits
}

__global__ __launch_bounds__(THREADS) void chamfer_kernel(
    const float* __restrict__ x, const float* __restrict__ y) {
    __shared__ float4 sy[YT];  // 32 KB

    const int yc   = blockIdx.x;
    const int xc   = blockIdx.y;
    const int dirb = blockIdx.z;
    const int dir  = dirb >> 3;
    const int b    = dirb & 7;

    // dir 0: A = x (query), P = y (points).  dir 1: swapped.
    const float* A = dir ? y : x;
    const float* P = dir ? x : y;
    const float* Ab = A + b * 3 * NP;
    const float* Pb = P + b * 3 * NP;

    const int tid = threadIdx.x;

    // Stage point tile into shared as float4 for single-LDS.128 broadcast reads.
    for (int j = tid; j < YT; j += THREADS) {
        int gj = yc * YT + j;
        sy[j] = make_float4(Pb[gj], Pb[NP + gj], Pb[2 * NP + gj], 0.0f);
    }
    __syncthreads();

    float ax[ILX], ay[ILX], az[ILX], mn[ILX];
#pragma unroll
    for (int k = 0; k < ILX; k++) {
        int gi = xc * XCHUNK + k * THREADS + tid;
        ax[k] = Ab[gi];
        ay[k] = Ab[NP + gi];
        az[k] = Ab[2 * NP + gi];
        mn[k] = CUDART_INF_F;
    }

#pragma unroll 4
    for (int j = 0; j < YT; j++) {
        float4 p = sy[j];
#pragma unroll
        for (int k = 0; k < ILX; k++) {
            float d0 = ax[k] - p.x;
            float d1 = ay[k] - p.y;
            float d2 = az[k] - p.z;
            float d  = fmaf(d2, d2, fmaf(d1, d1, d0 * d0));
            mn[k]    = fminf(mn[k], d);
        }
    }

    int* gm = g_min + (dir * NB + b) * NP;
#pragma unroll
    for (int k = 0; k < ILX; k++) {
        int gi = xc * XCHUNK + k * THREADS + tid;
        atomicMin(&gm[gi], __float_as_int(mn[k]));
    }
}

__global__ void reduce_kernel(float* __restrict__ out) {
    __shared__ float sred[256];
    float s = 0.0f;
    for (int i = threadIdx.x; i < 2 * NB * NP; i += 256)
        s += __int_as_float(g_min[i]);
    sred[threadIdx.x] = s;
    __syncthreads();
    for (int w = 128; w > 0; w >>= 1) {
        if (threadIdx.x < w) sred[threadIdx.x] += sred[threadIdx.x + w];
        __syncthreads();
    }
    if (threadIdx.x == 0) {
        // mean_b( sum_minx/NP + sum_miny/NP ) = total_sum / (NB*NP)
        out[0] = sred[0] / (float)(NB * NP);
    }
}

extern "C" void kernel_launch(void* const* d_in, const int* in_sizes, int n_in,
                              void* d_out, int out_size) {
    const float* x = (const float*)d_in[0];
    const float* y = (const float*)d_in[1];
    float* out = (float*)d_out;

    init_min_kernel<<<(2 * NB * NP + 255) / 256, 256>>>();
    dim3 grid(YC, XC, 2 * NB);
    chamfer_kernel<<<grid, THREADS>>>(x, y);
    reduce_kernel<<<1, 256>>>(out);
}